// round 3
// baseline (speedup 1.0000x reference)
#include <cuda_runtime.h>
#include <math.h>

#define Kq    4096
#define Mq    4
#define Dq    32
#define HWq   1024
#define EPSF  1e-7f
#define NEGINF -1e9f

// Output layout: [sample | code | one_hot | logit], all float32
#define SAMPLE_OFF 0ull
#define CODE_OFF   67108864ull
#define ONEHOT_OFF 67125248ull
#define LOGIT_OFF  134234112ull

__device__ float g_expo;
__device__ float g_thresh[Mq * Kq];
__device__ float g_c2[Mq * Kq];

// ---------------- Kernel 1: code_usage -> expo ----------------
__global__ void k_usage(const float* __restrict__ freq) {
    __shared__ int warpsum[8];
    int tid = threadIdx.x;
    int c = 0;
    for (int i = tid; i < Mq * Kq; i += 256) c += (freq[i] > EPSF) ? 1 : 0;
    for (int o = 16; o; o >>= 1) c += __shfl_down_sync(0xffffffffu, c, o);
    if ((tid & 31) == 0) warpsum[tid >> 5] = c;
    __syncthreads();
    if (tid == 0) {
        int t = 0;
        for (int w = 0; w < 8; ++w) t += warpsum[w];
        float cu = (float)t * (1.0f / 16384.0f);
        cu = fminf(fmaxf(cu, 0.0f), 1.0f);
        g_expo = 12.0f - 11.0f * (cu * cu);
    }
}

// ---------------- Kernel 2: thresh + codeword norms ----------------
__global__ void k_prep(const float* __restrict__ freq, const float* __restrict__ cb) {
    int i = blockIdx.x * blockDim.x + threadIdx.x;
    if (i >= Mq * Kq) return;
    const float* c = cb + (size_t)i * Dq;
    float s = 0.0f;
    #pragma unroll
    for (int d = 0; d < Dq; ++d) s += c[d] * c[d];
    g_c2[i] = s;
    float f = freq[i];
    float th = -1.0f;
    if (f > 0.0f) {
        double ie = 1.0 / (double)g_expo;
        th = (float)pow((double)f, ie);   // drop^expo < f  <=>  drop < f^(1/expo)
    }
    g_thresh[i] = th;
}

// ---------------- Kernel 3: fused main ----------------
// 2048 blocks x 512 threads; block = one (n,m), 8 positions.
// 8 codebook tiles of 512 rows, single smem buffer, register-prefetched.
// s values staged in SMEM (frees registers, enables float4 finale).
__global__ __launch_bounds__(512, 1) void k_main(
    const float* __restrict__ x, const float* __restrict__ cb,
    const float* __restrict__ temp,
    const float* __restrict__ drop, const float* __restrict__ gum,
    float* __restrict__ out)
{
    extern __shared__ float sm[];
    float* cbs     = sm;                    // 512*33 = 16896 floats
    float* s_sm    = sm + 16896;            // 8*4096 = 32768 floats
    float* xvs     = s_sm + 32768;          // 256
    float* x2s     = xvs + 256;             // 8
    float* scV     = x2s + 8;               // 64
    float* scV2    = scV + 64;              // 64
    float* scS     = scV2 + 64;             // 64
    float* finSmax = scS + 64;              // 8
    float* finInv  = finSmax + 8;           // 8
    int*   scI     = (int*)(finInv + 8);    // 64
    int*   scI2    = scI + 64;              // 64
    int*   finSidx = scI2 + 64;             // 8
    int*   finLidx = finSidx + 8;           // 8

    const int tid  = threadIdx.x;
    const int bid  = blockIdx.x;
    const int nm   = bid >> 7;
    const int m    = nm & 3;
    const int hw0  = (bid & 127) << 3;
    const long posBase = (long)nm * HWq + hw0;

    const int g    = tid >> 8;              // 0/1
    const int jj   = tid & 255;
    const int wig  = (tid >> 5) & 7;
    const int lane = tid & 31;

    if (tid < 256) {
        int p = tid & 7, d = tid >> 3;
        xvs[p * 32 + d] = x[((size_t)(nm * Dq + d)) * HWq + hw0 + p];
    }
    __syncthreads();
    if (tid < 8) {
        float s = 0.0f;
        #pragma unroll
        for (int d = 0; d < 32; ++d) { float v = xvs[tid * 32 + d]; s += v * v; }
        x2s[tid] = s;
    }
    __syncthreads();

    const float lbt = fmaxf(temp[m], EPSF);
    const float4* cb4 = (const float4*)(cb + (size_t)m * Kq * Dq);
    const float* c2m = g_c2 + m * Kq;
    const float* thm = g_thresh + m * Kq;

    float x2r[4];
    #pragma unroll
    for (int p = 0; p < 4; ++p) x2r[p] = x2s[g * 4 + p];

    float lmv[4], smv[4]; int lix[4], six[4];
    #pragma unroll
    for (int p = 0; p < 4; ++p) { lmv[p] = -3.4e38f; smv[p] = -3.4e38f; lix[p] = 0; six[p] = 0; }

    // Prefetch tile 0 into registers, stage to smem
    float4 pf[8];
    #pragma unroll
    for (int i = 0; i < 8; ++i) pf[i] = cb4[(size_t)(i * 512 + tid)];
    #pragma unroll
    for (int i = 0; i < 8; ++i) {
        int idx = i * 512 + tid, row = idx >> 3, d4 = idx & 7;
        float* dst = &cbs[row * 33 + (d4 << 2)];
        dst[0] = pf[i].x; dst[1] = pf[i].y; dst[2] = pf[i].z; dst[3] = pf[i].w;
    }
    __syncthreads();

    for (int t = 0; t < 8; ++t) {
        // Prefetch next tile into registers (hidden under compute below)
        if (t < 7) {
            #pragma unroll
            for (int i = 0; i < 8; ++i)
                pf[i] = cb4[(size_t)((t + 1) * 4096 + i * 512 + tid)];
        }

        // Hoist the per-k constants so their loads join the prefetch batch
        float c2k0 = __ldg(c2m + t * 512 + jj);
        float th0  = __ldg(thm + t * 512 + jj);
        float c2k1 = __ldg(c2m + t * 512 + 256 + jj);
        float th1  = __ldg(thm + t * 512 + 256 + jj);

        // Register-tiled dot products: 2 k x 4 positions per thread
        float acc[2][4];
        #pragma unroll
        for (int c = 0; c < 2; ++c)
            #pragma unroll
            for (int p = 0; p < 4; ++p) acc[c][p] = 0.0f;

        #pragma unroll
        for (int dc = 0; dc < 8; ++dc) {
            float xvr[4][4];
            #pragma unroll
            for (int p = 0; p < 4; ++p)
                #pragma unroll
                for (int dd = 0; dd < 4; ++dd)
                    xvr[p][dd] = xvs[(g * 4 + p) * 32 + dc * 4 + dd];
            #pragma unroll
            for (int c = 0; c < 2; ++c) {
                const float* cr = &cbs[(c * 256 + jj) * 33 + dc * 4];
                #pragma unroll
                for (int dd = 0; dd < 4; ++dd) {
                    float cv = cr[dd];
                    #pragma unroll
                    for (int p = 0; p < 4; ++p)
                        acc[c][p] = fmaf(cv, xvr[p][dd], acc[c][p]);
                }
            }
        }

        // Epilogue: logit + drop + gumbel, streaming stores, s to smem
        #pragma unroll
        for (int c = 0; c < 2; ++c) {
            int k = t * 512 + c * 256 + jj;
            float c2k = c ? c2k1 : c2k0;
            float th  = c ? th1  : th0;
            #pragma unroll
            for (int p = 0; p < 4; ++p) {
                int pp = g * 4 + p;
                size_t off = ((size_t)(posBase + pp)) * Kq + k;
                float dist = (x2r[p] + c2k) - 2.0f * acc[c][p];
                float lg = (dist * -0.015625f) * lbt;
                float dn = __ldcs(drop + off);
                if (dn < th) lg += NEGINF;
                float gn = __ldcs(gum + off);
                float s = lg + gn;
                __stcs(out + LOGIT_OFF + off, lg);
                if (lg > lmv[p]) { lmv[p] = lg; lix[p] = k; }
                if (s  > smv[p]) { smv[p] = s;  six[p] = k; }
                s_sm[pp * 4096 + k] = s;
            }
        }
        __syncthreads();   // all reads of cbs done

        if (t < 7) {
            #pragma unroll
            for (int i = 0; i < 8; ++i) {
                int idx = i * 512 + tid, row = idx >> 3, d4 = idx & 7;
                float* dst = &cbs[row * 33 + (d4 << 2)];
                dst[0] = pf[i].x; dst[1] = pf[i].y; dst[2] = pf[i].z; dst[3] = pf[i].w;
            }
            __syncthreads();
        }
    }

    // Block-wide argmax reductions (tie -> lowest k)
    #pragma unroll
    for (int p = 0; p < 4; ++p) {
        int pp = g * 4 + p;
        float v = lmv[p]; int ix = lix[p];
        for (int o = 16; o; o >>= 1) {
            float ov = __shfl_down_sync(0xffffffffu, v, o);
            int   oi = __shfl_down_sync(0xffffffffu, ix, o);
            if (ov > v || (ov == v && oi < ix)) { v = ov; ix = oi; }
        }
        if (lane == 0) { scV[pp * 8 + wig] = v; scI[pp * 8 + wig] = ix; }
        v = smv[p]; ix = six[p];
        for (int o = 16; o; o >>= 1) {
            float ov = __shfl_down_sync(0xffffffffu, v, o);
            int   oi = __shfl_down_sync(0xffffffffu, ix, o);
            if (ov > v || (ov == v && oi < ix)) { v = ov; ix = oi; }
        }
        if (lane == 0) { scV2[pp * 8 + wig] = v; scI2[pp * 8 + wig] = ix; }
    }
    __syncthreads();
    if (tid < 8) {
        float bv = -3.4e38f; int bi = 0;
        for (int w = 0; w < 8; ++w) {
            float v = scV[tid * 8 + w]; int i2 = scI[tid * 8 + w];
            if (v > bv || (v == bv && i2 < bi)) { bv = v; bi = i2; }
        }
        finLidx[tid] = bi;
        bv = -3.4e38f; bi = 0;
        for (int w = 0; w < 8; ++w) {
            float v = scV2[tid * 8 + w]; int i2 = scI2[tid * 8 + w];
            if (v > bv || (v == bv && i2 < bi)) { bv = v; bi = i2; }
        }
        finSmax[tid] = bv; finSidx[tid] = bi;
    }
    __syncthreads();

    // Softmax denominator: read s (transposed float4 mapping, conflict-free)
    const float4* s4 = (const float4*)s_sm;
    #pragma unroll
    for (int p = 0; p < 4; ++p) {
        int pp = g * 4 + p;
        float mx = finSmax[pp];
        float s = 0.0f;
        #pragma unroll
        for (int i = 0; i < 4; ++i) {
            float4 sv = s4[pp * 1024 + i * 256 + jj];
            s += __expf(sv.x - mx) + __expf(sv.y - mx)
               + __expf(sv.z - mx) + __expf(sv.w - mx);
        }
        for (int o = 16; o; o >>= 1) s += __shfl_down_sync(0xffffffffu, s, o);
        if (lane == 0) scS[pp * 8 + wig] = s;
    }
    __syncthreads();
    if (tid < 8) {
        float s = 0.0f;
        for (int w = 0; w < 8; ++w) s += scS[tid * 8 + w];
        finInv[tid] = 1.0f / s;
        out[CODE_OFF + (size_t)(posBase + tid)] = (float)finLidx[tid];
    }
    __syncthreads();

    // Finale: float4 streaming stores of sample + one_hot
    float4* outS4 = (float4*)out;                       // SAMPLE_OFF = 0
    float4* outO4 = (float4*)(out + ONEHOT_OFF);
    #pragma unroll
    for (int p = 0; p < 4; ++p) {
        int pp = g * 4 + p;
        float mx = finSmax[pp], inv = finInv[pp];
        int si = finSidx[pp], li = finLidx[pp];
        size_t base4 = ((size_t)(posBase + pp)) * 1024;  // in float4 units
        #pragma unroll
        for (int i = 0; i < 4; ++i) {
            int k0 = i * 1024 + jj * 4;
            float4 sv = s4[pp * 1024 + i * 256 + jj];
            float4 smp, oh;
            {
                float y = __expf(sv.x - mx) * inv;
                float h = (k0 + 0 == si) ? 1.0f : 0.0f;
                smp.x = (h + y) - y; oh.x = (k0 + 0 == li) ? 1.0f : 0.0f;
            }
            {
                float y = __expf(sv.y - mx) * inv;
                float h = (k0 + 1 == si) ? 1.0f : 0.0f;
                smp.y = (h + y) - y; oh.y = (k0 + 1 == li) ? 1.0f : 0.0f;
            }
            {
                float y = __expf(sv.z - mx) * inv;
                float h = (k0 + 2 == si) ? 1.0f : 0.0f;
                smp.z = (h + y) - y; oh.z = (k0 + 2 == li) ? 1.0f : 0.0f;
            }
            {
                float y = __expf(sv.w - mx) * inv;
                float h = (k0 + 3 == si) ? 1.0f : 0.0f;
                smp.w = (h + y) - y; oh.w = (k0 + 3 == li) ? 1.0f : 0.0f;
            }
            __stcs(outS4 + base4 + i * 256 + jj, smp);
            __stcs(outO4 + base4 + i * 256 + jj, oh);
        }
    }
}

// ---------------- launch ----------------
extern "C" void kernel_launch(void* const* d_in, const int* in_sizes, int n_in,
                              void* d_out, int out_size) {
    const float* x    = (const float*)d_in[0];
    const float* cb   = (const float*)d_in[1];
    const float* freq = (const float*)d_in[2];
    const float* temp = (const float*)d_in[3];
    const float* drop = (const float*)d_in[4];
    const float* gum  = (const float*)d_in[5];
    float* out = (float*)d_out;

    const int smemBytes = (16896 + 32768 + 256 + 8 + 64 * 3 + 8 * 2 + 64 * 2 + 8 * 2) * 4;
    cudaFuncSetAttribute(k_main, cudaFuncAttributeMaxDynamicSharedMemorySize, smemBytes);

    k_usage<<<1, 256>>>(freq);
    k_prep<<<64, 256>>>(freq, cb);
    k_main<<<2048, 512, smemBytes>>>(x, cb, temp, drop, gum, out);
}

// round 4
// speedup vs baseline: 1.3502x; 1.3502x over previous
#include <cuda_runtime.h>
#include <math.h>

#define Kq    4096
#define Mq    4
#define Dq    32
#define HWq   1024
#define EPSF  1e-7f
#define NEGINF -1e9f

// Output layout: [sample | code | one_hot | logit], all float32
#define SAMPLE_OFF 0ull
#define CODE_OFF   67108864ull
#define ONEHOT_OFF 67125248ull
#define LOGIT_OFF  134234112ull

__device__ float g_thresh[Mq * Kq];
__device__ float g_c2[Mq * Kq];

// ---------------- Kernel 1: usage + thresh + codeword norms (single block) ----------------
__global__ void k_prep_all(const float* __restrict__ freq, const float* __restrict__ cb) {
    __shared__ int wsum[32];
    __shared__ float expo_s;
    const int tid = threadIdx.x;        // 1024 threads
    const int lane = tid & 31;

    int c = 0;
    for (int i = tid; i < Mq * Kq; i += 1024) c += (freq[i] > EPSF) ? 1 : 0;
    for (int o = 16; o; o >>= 1) c += __shfl_down_sync(0xffffffffu, c, o);
    if (lane == 0) wsum[tid >> 5] = c;
    __syncthreads();
    if (tid == 0) {
        int t = 0;
        for (int w = 0; w < 32; ++w) t += wsum[w];
        float cu = (float)t * (1.0f / 16384.0f);
        cu = fminf(fmaxf(cu, 0.0f), 1.0f);
        expo_s = 12.0f - 11.0f * (cu * cu);   // -(BITS-1)*cu^2 + BITS
    }
    __syncthreads();
    const double ie = 1.0 / (double)expo_s;

    const float4* cb4 = (const float4*)cb;
    for (int i = tid; i < Mq * Kq; i += 1024) {
        float s = 0.0f;
        #pragma unroll
        for (int j = 0; j < 8; ++j) {
            float4 v = cb4[(size_t)i * 8 + j];
            s += v.x * v.x + v.y * v.y + v.z * v.z + v.w * v.w;
        }
        g_c2[i] = s;
        float f = freq[i];
        float th = -1.0f;                      // drop >= 0 always -> never drop
        if (f > 0.0f) th = (float)pow((double)f, ie);  // drop^e < f <=> drop < f^(1/e)
        g_thresh[i] = th;
    }
}

// ---------------- Kernel 2: fused main ----------------
// 2048 blocks x 512 threads, 2 CTAs/SM. Block = one (n,m), 8 positions.
// 8 codebook tiles of 512 rows in 67.6KB smem. No softmax: sample == one_hot(argmax s)
// to within 1 ulp, so only running argmaxes are kept; sample/one_hot are zero-filled
// up front (stores drain under the GEMM) and the two 1.0s scattered at the end.
__global__ __launch_bounds__(512, 2) void k_main(
    const float* __restrict__ x, const float* __restrict__ cb,
    const float* __restrict__ temp,
    const float* __restrict__ drop, const float* __restrict__ gum,
    float* __restrict__ out)
{
    extern __shared__ float sm[];
    float* cbs  = sm;                    // 512*33 = 16896 floats (67.6 KB)
    float* xvs  = sm + 16896;            // 256
    float* x2s  = xvs + 256;             // 8
    float* scV  = x2s + 8;               // 64  logit argmax vals
    float* scV2 = scV + 64;              // 64  s argmax vals
    int*   scI  = (int*)(scV2 + 64);     // 64
    int*   scI2 = scI + 64;              // 64

    const int tid  = threadIdx.x;
    const int bid  = blockIdx.x;
    const int nm   = bid >> 7;
    const int m    = nm & 3;
    const int hw0  = (bid & 127) << 3;
    const long posBase = (long)nm * HWq + hw0;

    const int g    = tid >> 8;           // 0/1: positions g*4 .. g*4+3
    const int jj   = tid & 255;
    const int wig  = (tid >> 5) & 7;     // warp within group
    const int lane = tid & 31;

    // --- Zero-fill sample & one_hot first: pure stores, drain under the GEMM ---
    {
        const float4 z4 = make_float4(0.f, 0.f, 0.f, 0.f);
        float4* outS4 = (float4*)out;                     // SAMPLE_OFF = 0
        float4* outO4 = (float4*)(out + ONEHOT_OFF);
        const size_t base4 = (size_t)posBase * 1024;      // 8 pos * 1024 float4
        #pragma unroll
        for (int i = 0; i < 16; ++i) {
            __stcs(outS4 + base4 + i * 512 + tid, z4);
            __stcs(outO4 + base4 + i * 512 + tid, z4);
        }
    }

    // --- Load x vectors for the 8 positions ---
    if (tid < 256) {
        int p = tid & 7, d = tid >> 3;
        xvs[p * 32 + d] = x[((size_t)(nm * Dq + d)) * HWq + hw0 + p];
    }
    __syncthreads();
    if (tid < 8) {
        float s = 0.0f;
        #pragma unroll
        for (int d = 0; d < 32; ++d) { float v = xvs[tid * 32 + d]; s += v * v; }
        x2s[tid] = s;
    }
    __syncthreads();

    const float lbt = fmaxf(temp[m], EPSF);          // lower_bound(temperature)
    const float4* cb4 = (const float4*)(cb + (size_t)m * Kq * Dq);
    const float* c2m = g_c2 + m * Kq;
    const float* thm = g_thresh + m * Kq;

    float x2r[4];
    #pragma unroll
    for (int p = 0; p < 4; ++p) x2r[p] = x2s[g * 4 + p];

    float lmv[4], smv[4]; int lix[4], six[4];
    #pragma unroll
    for (int p = 0; p < 4; ++p) { lmv[p] = -3.4e38f; smv[p] = -3.4e38f; lix[p] = 0; six[p] = 0; }

    for (int t = 0; t < 8; ++t) {
        // Cooperative load of 512-codeword tile (stride 33 -> conflict-free LDS)
        #pragma unroll
        for (int i = 0; i < 8; ++i) {
            int idx = i * 512 + tid, row = idx >> 3, d4 = idx & 7;
            float4 v = cb4[(size_t)(t * 512 + row) * 8 + d4];
            float* dst = &cbs[row * 33 + (d4 << 2)];
            dst[0] = v.x; dst[1] = v.y; dst[2] = v.z; dst[3] = v.w;
        }
        __syncthreads();

        // Register-tiled dots: 2 k x 4 positions per thread
        float acc[2][4];
        #pragma unroll
        for (int c = 0; c < 2; ++c)
            #pragma unroll
            for (int p = 0; p < 4; ++p) acc[c][p] = 0.0f;

        #pragma unroll
        for (int dc = 0; dc < 8; ++dc) {
            float xvr[4][4];
            #pragma unroll
            for (int p = 0; p < 4; ++p)
                #pragma unroll
                for (int dd = 0; dd < 4; ++dd)
                    xvr[p][dd] = xvs[(g * 4 + p) * 32 + dc * 4 + dd];
            #pragma unroll
            for (int c = 0; c < 2; ++c) {
                const float* cr = &cbs[(c * 256 + jj) * 33 + dc * 4];
                #pragma unroll
                for (int dd = 0; dd < 4; ++dd) {
                    float cv = cr[dd];
                    #pragma unroll
                    for (int p = 0; p < 4; ++p)
                        acc[c][p] = fmaf(cv, xvr[p][dd], acc[c][p]);
                }
            }
        }

        // Epilogue: logit + drop + gumbel; streaming logit store; running argmaxes
        #pragma unroll
        for (int c = 0; c < 2; ++c) {
            int k = t * 512 + c * 256 + jj;
            float c2k = __ldg(c2m + k);
            float th  = __ldg(thm + k);
            #pragma unroll
            for (int p = 0; p < 4; ++p) {
                int pp = g * 4 + p;
                size_t off = ((size_t)(posBase + pp)) * Kq + k;
                float dist = (x2r[p] + c2k) - 2.0f * acc[c][p];
                float lg = (dist * -0.015625f) * lbt;      // (-dist/64)*lb(temp)
                float dn = __ldcs(drop + off);
                if (dn < th) lg += NEGINF;
                float gn = __ldcs(gum + off);
                float s = lg + gn;
                __stcs(out + LOGIT_OFF + off, lg);
                if (lg > lmv[p]) { lmv[p] = lg; lix[p] = k; }
                if (s  > smv[p]) { smv[p] = s;  six[p] = k; }
            }
        }
        __syncthreads();   // all reads of cbs done before next tile overwrites
    }

    // --- Block-wide argmax reductions (tie -> lowest k, matching jnp.argmax) ---
    #pragma unroll
    for (int p = 0; p < 4; ++p) {
        int pp = g * 4 + p;
        float v = lmv[p]; int ix = lix[p];
        for (int o = 16; o; o >>= 1) {
            float ov = __shfl_down_sync(0xffffffffu, v, o);
            int   oi = __shfl_down_sync(0xffffffffu, ix, o);
            if (ov > v || (ov == v && oi < ix)) { v = ov; ix = oi; }
        }
        if (lane == 0) { scV[pp * 8 + wig] = v; scI[pp * 8 + wig] = ix; }
        v = smv[p]; ix = six[p];
        for (int o = 16; o; o >>= 1) {
            float ov = __shfl_down_sync(0xffffffffu, v, o);
            int   oi = __shfl_down_sync(0xffffffffu, ix, o);
            if (ov > v || (ov == v && oi < ix)) { v = ov; ix = oi; }
        }
        if (lane == 0) { scV2[pp * 8 + wig] = v; scI2[pp * 8 + wig] = ix; }
    }
    __syncthreads();   // also orders the zero-fill stores before the scatters below

    if (tid < 8) {
        // final combine over the 8 warps of the owning group
        float bv = -3.4e38f; int li = 0;
        for (int w = 0; w < 8; ++w) {
            float v = scV[tid * 8 + w]; int i2 = scI[tid * 8 + w];
            if (v > bv || (v == bv && i2 < li)) { bv = v; li = i2; }
        }
        bv = -3.4e38f; int si = 0;
        for (int w = 0; w < 8; ++w) {
            float v = scV2[tid * 8 + w]; int i2 = scI2[tid * 8 + w];
            if (v > bv || (v == bv && i2 < si)) { bv = v; si = i2; }
        }
        size_t base = ((size_t)(posBase + tid)) * Kq;
        out[CODE_OFF + (size_t)(posBase + tid)] = (float)li;
        out[ONEHOT_OFF + base + li] = 1.0f;
        out[SAMPLE_OFF + base + si] = 1.0f;   // (1+y)-y == 1.0 within 1 ulp
    }
}

// ---------------- launch ----------------
extern "C" void kernel_launch(void* const* d_in, const int* in_sizes, int n_in,
                              void* d_out, int out_size) {
    const float* x    = (const float*)d_in[0];
    const float* cb   = (const float*)d_in[1];
    const float* freq = (const float*)d_in[2];
    const float* temp = (const float*)d_in[3];
    const float* drop = (const float*)d_in[4];
    const float* gum  = (const float*)d_in[5];
    float* out = (float*)d_out;

    const int smemBytes = (16896 + 256 + 8 + 64 * 2) * 4 + (64 * 2) * 4;  // ~69.7 KB
    cudaFuncSetAttribute(k_main, cudaFuncAttributeMaxDynamicSharedMemorySize, smemBytes);

    k_prep_all<<<1, 1024>>>(freq, cb);
    k_main<<<2048, 512, smemBytes>>>(x, cb, temp, drop, gum, out);
}

// round 6
// speedup vs baseline: 1.7955x; 1.3298x over previous
#include <cuda_runtime.h>
#include <math.h>
#include <stdint.h>

#define Kq    4096
#define Mq    4
#define Dq    32
#define HWq   1024
#define EPSF  1e-7f
#define NEGINF -1e9f

// Output layout: [sample | code | one_hot | logit], all float32
#define SAMPLE_OFF 0ull
#define CODE_OFF   67108864ull
#define ONEHOT_OFF 67125248ull
#define LOGIT_OFF  134234112ull

__device__ float g_thresh[Mq * Kq];
__device__ float g_c2[Mq * Kq];

__device__ __forceinline__ void cp16(uint32_t dst_smem, const void* src) {
    asm volatile("cp.async.cg.shared.global [%0], [%1], 16;" :: "r"(dst_smem), "l"(src));
}

// ---------------- Kernel 1: usage + thresh + codeword norms (single block) ----------------
__global__ void k_prep_all(const float* __restrict__ freq, const float* __restrict__ cb) {
    __shared__ int wsum[32];
    __shared__ float expo_s;
    const int tid = threadIdx.x;        // 1024 threads
    const int lane = tid & 31;

    int c = 0;
    for (int i = tid; i < Mq * Kq; i += 1024) c += (freq[i] > EPSF) ? 1 : 0;
    for (int o = 16; o; o >>= 1) c += __shfl_down_sync(0xffffffffu, c, o);
    if (lane == 0) wsum[tid >> 5] = c;
    __syncthreads();
    if (tid == 0) {
        int t = 0;
        for (int w = 0; w < 32; ++w) t += wsum[w];
        float cu = (float)t * (1.0f / 16384.0f);
        cu = fminf(fmaxf(cu, 0.0f), 1.0f);
        expo_s = 12.0f - 11.0f * (cu * cu);   // -(BITS-1)*cu^2 + BITS
    }
    __syncthreads();
    const double ie = 1.0 / (double)expo_s;

    const float4* cb4 = (const float4*)cb;
    for (int i = tid; i < Mq * Kq; i += 1024) {
        float s = 0.0f;
        #pragma unroll
        for (int j = 0; j < 8; ++j) {
            float4 v = cb4[(size_t)i * 8 + j];
            s += v.x * v.x + v.y * v.y + v.z * v.z + v.w * v.w;
        }
        g_c2[i] = s;
        float f = freq[i];
        float th = -1.0f;                      // drop >= 0 always -> never drop
        if (f > 0.0f) th = (float)pow((double)f, ie);  // drop^e < f <=> drop < f^(1/e)
        g_thresh[i] = th;
    }
}

// ---------------- Kernel 2: fused main ----------------
// 2048 blocks x 512 threads, 2 CTAs/SM. Block = one (n,m), 8 positions.
// Thread -> 4 consecutive k x 2 positions => 128-bit LDG/STG on all streaming traffic.
// Codebook tile (512 rows) in smem, permuted slots + stride-36 => conflict-free LDS.128.
// cp.async fill keeps registers free. No softmax (sample == one_hot(argmax s) within 1 ulp).
__global__ __launch_bounds__(512, 2) void k_main(
    const float* __restrict__ x, const float* __restrict__ cb,
    const float* __restrict__ temp,
    const float* __restrict__ drop, const float* __restrict__ gum,
    float* __restrict__ out)
{
    extern __shared__ float sm[];
    float* cbs  = sm;                    // 512 slots * 36 = 18432 floats (73.7 KB)
    float* xvs  = sm + 18432;            // 256
    float* x2s  = xvs + 256;             // 8
    float* scV  = x2s + 8;               // 32 (8 pos x 4 warps) logit argmax vals
    float* scV2 = scV + 32;              // 32 s argmax vals
    int*   scI  = (int*)(scV2 + 32);     // 32
    int*   scI2 = scI + 32;              // 32

    const int tid  = threadIdx.x;
    const int bid  = blockIdx.x;
    const int nm   = bid >> 7;
    const int m    = nm & 3;
    const int hw0  = (bid & 127) << 3;
    const long posBase = (long)nm * HWq + hw0;

    const int grp  = tid >> 7;           // 0..3 -> positions grp*2, grp*2+1
    const int jj   = tid & 127;          // k sub-index: k = t*512 + 4*jj + c
    const int wig  = (tid >> 5) & 3;     // warp within group
    const int lane = tid & 31;
    const int pp0  = grp * 2, pp1 = pp0 + 1;

    // --- Zero-fill sample & one_hot first: pure stores, drain under the GEMM ---
    {
        const float4 z4 = make_float4(0.f, 0.f, 0.f, 0.f);
        float4* outS4 = (float4*)out;                     // SAMPLE_OFF = 0
        float4* outO4 = (float4*)(out + ONEHOT_OFF);
        const size_t base4 = (size_t)posBase * 1024;      // 8 pos * 1024 float4
        #pragma unroll
        for (int i = 0; i < 16; ++i) {
            __stcs(outS4 + base4 + i * 512 + tid, z4);
            __stcs(outO4 + base4 + i * 512 + tid, z4);
        }
    }

    // --- Load x vectors for the 8 positions ---
    if (tid < 256) {
        int p = tid & 7, d = tid >> 3;
        xvs[p * 32 + d] = x[((size_t)(nm * Dq + d)) * HWq + hw0 + p];
    }
    __syncthreads();
    if (tid < 8) {
        float s = 0.0f;
        #pragma unroll
        for (int d = 0; d < 32; ++d) { float v = xvs[tid * 32 + d]; s += v * v; }
        x2s[tid] = s;
    }
    __syncthreads();

    const float lbt = fmaxf(temp[m], EPSF);          // lower_bound(temperature)
    const float4* cb4 = (const float4*)(cb + (size_t)m * Kq * Dq);
    const float* c2m = g_c2 + m * Kq;
    const float* thm = g_thresh + m * Kq;
    const uint32_t cbs_base = (uint32_t)__cvta_generic_to_shared(cbs);

    const float x2a = x2s[pp0];
    const float x2b = x2s[pp1];
    const size_t offBase0 = ((size_t)(posBase + pp0)) * Kq;
    const size_t offBase1 = ((size_t)(posBase + pp1)) * Kq;

    float lmv[2], smv[2]; int lix[2], six[2];
    #pragma unroll
    for (int p = 0; p < 2; ++p) { lmv[p] = -3.4e38f; smv[p] = -3.4e38f; lix[p] = 0; six[p] = 0; }

    for (int t = 0; t < 8; ++t) {
        // --- cp.async fill of 512-row tile into permuted stride-36 layout ---
        #pragma unroll
        for (int i = 0; i < 8; ++i) {
            int idx = i * 512 + tid;
            int row = idx >> 3, d4 = idx & 7;
            uint32_t dst = cbs_base + (uint32_t)((((row >> 2) + (row & 3) * 128) * 36 + d4 * 4) * 4);
            cp16(dst, cb4 + (size_t)(t * 512 + row) * 8 + d4);
        }
        asm volatile("cp.async.commit_group;");
        asm volatile("cp.async.wait_group 0;");
        __syncthreads();

        // --- Register-tiled dots: 4 consecutive k x 2 positions ---
        float acc[4][2];
        #pragma unroll
        for (int c = 0; c < 4; ++c) { acc[c][0] = 0.0f; acc[c][1] = 0.0f; }

        #pragma unroll
        for (int dc = 0; dc < 8; ++dc) {
            const float4 xa = *(const float4*)&xvs[pp0 * 32 + dc * 4];
            const float4 xb = *(const float4*)&xvs[pp1 * 32 + dc * 4];
            #pragma unroll
            for (int c = 0; c < 4; ++c) {
                const float4 cv = *(const float4*)&cbs[(c * 128 + jj) * 36 + dc * 4];
                acc[c][0] = fmaf(cv.x, xa.x, acc[c][0]);
                acc[c][0] = fmaf(cv.y, xa.y, acc[c][0]);
                acc[c][0] = fmaf(cv.z, xa.z, acc[c][0]);
                acc[c][0] = fmaf(cv.w, xa.w, acc[c][0]);
                acc[c][1] = fmaf(cv.x, xb.x, acc[c][1]);
                acc[c][1] = fmaf(cv.y, xb.y, acc[c][1]);
                acc[c][1] = fmaf(cv.z, xb.z, acc[c][1]);
                acc[c][1] = fmaf(cv.w, xb.w, acc[c][1]);
            }
        }

        // --- Epilogue: vector loads, logit/s, streaming 128-bit stores, argmaxes ---
        {
            const int k0 = t * 512 + 4 * jj;
            const float4 c2 = __ldg((const float4*)(c2m + k0));
            const float4 th = __ldg((const float4*)(thm + k0));
            const size_t off0 = offBase0 + k0;
            const size_t off1 = offBase1 + k0;
            const float4 dn0 = __ldcs((const float4*)(drop + off0));
            const float4 gn0 = __ldcs((const float4*)(gum  + off0));
            const float4 dn1 = __ldcs((const float4*)(drop + off1));
            const float4 gn1 = __ldcs((const float4*)(gum  + off1));

            float4 lg0, lg1;
            lg0.x = ((x2a + c2.x) - 2.0f * acc[0][0]) * -0.015625f * lbt;
            lg0.y = ((x2a + c2.y) - 2.0f * acc[1][0]) * -0.015625f * lbt;
            lg0.z = ((x2a + c2.z) - 2.0f * acc[2][0]) * -0.015625f * lbt;
            lg0.w = ((x2a + c2.w) - 2.0f * acc[3][0]) * -0.015625f * lbt;
            lg1.x = ((x2b + c2.x) - 2.0f * acc[0][1]) * -0.015625f * lbt;
            lg1.y = ((x2b + c2.y) - 2.0f * acc[1][1]) * -0.015625f * lbt;
            lg1.z = ((x2b + c2.z) - 2.0f * acc[2][1]) * -0.015625f * lbt;
            lg1.w = ((x2b + c2.w) - 2.0f * acc[3][1]) * -0.015625f * lbt;
            if (dn0.x < th.x) lg0.x += NEGINF;
            if (dn0.y < th.y) lg0.y += NEGINF;
            if (dn0.z < th.z) lg0.z += NEGINF;
            if (dn0.w < th.w) lg0.w += NEGINF;
            if (dn1.x < th.x) lg1.x += NEGINF;
            if (dn1.y < th.y) lg1.y += NEGINF;
            if (dn1.z < th.z) lg1.z += NEGINF;
            if (dn1.w < th.w) lg1.w += NEGINF;

            __stcs((float4*)(out + LOGIT_OFF + off0), lg0);
            __stcs((float4*)(out + LOGIT_OFF + off1), lg1);

            // running argmaxes (k ascending within thread -> strict > keeps lowest)
            float sv;
            if (lg0.x > lmv[0]) { lmv[0] = lg0.x; lix[0] = k0 + 0; }
            if (lg0.y > lmv[0]) { lmv[0] = lg0.y; lix[0] = k0 + 1; }
            if (lg0.z > lmv[0]) { lmv[0] = lg0.z; lix[0] = k0 + 2; }
            if (lg0.w > lmv[0]) { lmv[0] = lg0.w; lix[0] = k0 + 3; }
            if (lg1.x > lmv[1]) { lmv[1] = lg1.x; lix[1] = k0 + 0; }
            if (lg1.y > lmv[1]) { lmv[1] = lg1.y; lix[1] = k0 + 1; }
            if (lg1.z > lmv[1]) { lmv[1] = lg1.z; lix[1] = k0 + 2; }
            if (lg1.w > lmv[1]) { lmv[1] = lg1.w; lix[1] = k0 + 3; }
            sv = lg0.x + gn0.x; if (sv > smv[0]) { smv[0] = sv; six[0] = k0 + 0; }
            sv = lg0.y + gn0.y; if (sv > smv[0]) { smv[0] = sv; six[0] = k0 + 1; }
            sv = lg0.z + gn0.z; if (sv > smv[0]) { smv[0] = sv; six[0] = k0 + 2; }
            sv = lg0.w + gn0.w; if (sv > smv[0]) { smv[0] = sv; six[0] = k0 + 3; }
            sv = lg1.x + gn1.x; if (sv > smv[1]) { smv[1] = sv; six[1] = k0 + 0; }
            sv = lg1.y + gn1.y; if (sv > smv[1]) { smv[1] = sv; six[1] = k0 + 1; }
            sv = lg1.z + gn1.z; if (sv > smv[1]) { smv[1] = sv; six[1] = k0 + 2; }
            sv = lg1.w + gn1.w; if (sv > smv[1]) { smv[1] = sv; six[1] = k0 + 3; }
        }
        __syncthreads();   // all reads of cbs done before next fill overwrites
    }

    // --- Block-wide argmax reductions (tie -> lowest k, matching jnp.argmax) ---
    #pragma unroll
    for (int p = 0; p < 2; ++p) {
        int pp = pp0 + p;
        float v = lmv[p]; int ix = lix[p];
        for (int o = 16; o; o >>= 1) {
            float ov = __shfl_down_sync(0xffffffffu, v, o);
            int   oi = __shfl_down_sync(0xffffffffu, ix, o);
            if (ov > v || (ov == v && oi < ix)) { v = ov; ix = oi; }
        }
        if (lane == 0) { scV[pp * 4 + wig] = v; scI[pp * 4 + wig] = ix; }
        v = smv[p]; ix = six[p];
        for (int o = 16; o; o >>= 1) {
            float ov = __shfl_down_sync(0xffffffffu, v, o);
            int   oi = __shfl_down_sync(0xffffffffu, ix, o);
            if (ov > v || (ov == v && oi < ix)) { v = ov; ix = oi; }
        }
        if (lane == 0) { scV2[pp * 4 + wig] = v; scI2[pp * 4 + wig] = ix; }
    }
    __syncthreads();   // also orders the zero-fill stores before the scatters below

    if (tid < 8) {
        float bv = -3.4e38f; int li = 0;
        for (int w = 0; w < 4; ++w) {
            float v = scV[tid * 4 + w]; int i2 = scI[tid * 4 + w];
            if (v > bv || (v == bv && i2 < li)) { bv = v; li = i2; }
        }
        bv = -3.4e38f; int si = 0;
        for (int w = 0; w < 4; ++w) {
            float v = scV2[tid * 4 + w]; int i2 = scI2[tid * 4 + w];
            if (v > bv || (v == bv && i2 < si)) { bv = v; si = i2; }
        }
        size_t base = ((size_t)(posBase + tid)) * Kq;
        out[CODE_OFF + (size_t)(posBase + tid)] = (float)li;
        out[ONEHOT_OFF + base + li] = 1.0f;
        out[SAMPLE_OFF + base + si] = 1.0f;   // (1+y)-y == 1.0 within 1 ulp
    }
}

// ---------------- launch ----------------
extern "C" void kernel_launch(void* const* d_in, const int* in_sizes, int n_in,
                              void* d_out, int out_size) {
    const float* x    = (const float*)d_in[0];
    const float* cb   = (const float*)d_in[1];
    const float* freq = (const float*)d_in[2];
    const float* temp = (const float*)d_in[3];
    const float* drop = (const float*)d_in[4];
    const float* gum  = (const float*)d_in[5];
    float* out = (float*)d_out;

    const int smemBytes = (18432 + 256 + 8 + 32 * 2 + 32 * 2) * 4;  // ~74.9 KB
    cudaFuncSetAttribute(k_main, cudaFuncAttributeMaxDynamicSharedMemorySize, smemBytes);

    k_prep_all<<<1, 1024>>>(freq, cb);
    k_main<<<2048, 512, smemBytes>>>(x, cb, temp, drop, gum, out);
}

// round 7
// speedup vs baseline: 2.4271x; 1.3518x over previous
#include <cuda_runtime.h>
#include <math.h>
#include <stdint.h>

#define Kq    4096
#define Mq    4
#define Dq    32
#define HWq   1024
#define EPSF  1e-7f
#define NEGINF -1e9f

// Output layout: [sample | code | one_hot | logit], all float32
#define SAMPLE_OFF 0ull
#define CODE_OFF   67108864ull
#define ONEHOT_OFF 67125248ull
#define LOGIT_OFF  134234112ull

__device__ float g_expo;
__device__ float g_thresh[Mq * Kq];
__device__ float g_c2[Mq * Kq];

__device__ __forceinline__ void cp16(uint32_t dst_smem, const void* src) {
    asm volatile("cp.async.cg.shared.global [%0], [%1], 16;" :: "r"(dst_smem), "l"(src));
}

// ---------------- Kernel 1: code_usage -> expo (1 small block) ----------------
__global__ void k_usage(const float* __restrict__ freq) {
    __shared__ int wsum[8];
    const int tid = threadIdx.x;       // 256
    int c = 0;
    for (int i = tid; i < Mq * Kq; i += 256) c += (freq[i] > EPSF) ? 1 : 0;
    for (int o = 16; o; o >>= 1) c += __shfl_down_sync(0xffffffffu, c, o);
    if ((tid & 31) == 0) wsum[tid >> 5] = c;
    __syncthreads();
    if (tid == 0) {
        int t = 0;
        for (int w = 0; w < 8; ++w) t += wsum[w];
        float cu = (float)t * (1.0f / 16384.0f);
        cu = fminf(fmaxf(cu, 0.0f), 1.0f);
        g_expo = 12.0f - 11.0f * (cu * cu);   // -(BITS-1)*cu^2 + BITS
    }
}

// ---------------- Kernel 2: thresh + codeword norms (32 blocks) ----------------
__global__ void k_prep(const float* __restrict__ freq, const float* __restrict__ cb) {
    const int i = blockIdx.x * blockDim.x + threadIdx.x;  // 32*512 = 16384
    if (i >= Mq * Kq) return;
    const float4* c4 = (const float4*)(cb) + (size_t)i * 8;
    float s = 0.0f;
    #pragma unroll
    for (int j = 0; j < 8; ++j) {
        float4 v = c4[j];
        s += v.x * v.x + v.y * v.y + v.z * v.z + v.w * v.w;
    }
    g_c2[i] = s;
    float f = freq[i];
    float th = -1.0f;                      // drop >= 0 always -> never drop
    if (f > 0.0f) {
        double ie = 1.0 / (double)g_expo;
        th = (float)pow((double)f, ie);    // drop^e < f <=> drop < f^(1/e)
    }
    g_thresh[i] = th;
}

// ---------------- Kernel 3: fused main ----------------
// 1024 blocks x 512 threads, 2 CTAs/SM. Block = one (n,m), 16 positions.
// Thread -> 4 consecutive k x 4 positions: GEMM does 8 LDS.128 per 64 FMA.
// Codebook tile (512 rows) permuted stride-36 smem => conflict-free LDS.128;
// cp.async fill. No softmax (sample == one_hot(argmax s) within 1 ulp).
__global__ __launch_bounds__(512, 2) void k_main(
    const float* __restrict__ x, const float* __restrict__ cb,
    const float* __restrict__ temp,
    const float* __restrict__ drop, const float* __restrict__ gum,
    float* __restrict__ out)
{
    extern __shared__ float sm[];
    float* cbs  = sm;                    // 512 slots * 36 = 18432 floats (73.7 KB)
    float* xvs  = sm + 18432;            // 512 (16 pos x 32 d)
    float* x2s  = xvs + 512;             // 16
    float* scV  = x2s + 16;              // 64 (16 pos x 4 warps) logit argmax vals
    float* scV2 = scV + 64;              // 64 s argmax vals
    int*   scI  = (int*)(scV2 + 64);     // 64
    int*   scI2 = scI + 64;              // 64

    const int tid  = threadIdx.x;
    const int bid  = blockIdx.x;
    const int nm   = bid >> 6;           // 16 (n*M+m) values, 64 blocks each
    const int m    = nm & 3;
    const int hw0  = (bid & 63) << 4;    // 16 positions per block
    const long posBase = (long)nm * HWq + hw0;

    const int grp  = tid >> 7;           // 0..3 -> positions grp*4 .. grp*4+3
    const int jj   = tid & 127;          // k = t*512 + 4*jj + c
    const int wig  = (tid >> 5) & 3;     // warp within group
    const int lane = tid & 31;

    // --- Zero-fill sample & one_hot first: pure stores, drain under the GEMM ---
    {
        const float4 z4 = make_float4(0.f, 0.f, 0.f, 0.f);
        float4* outS4 = (float4*)out;                     // SAMPLE_OFF = 0
        float4* outO4 = (float4*)(out + ONEHOT_OFF);
        const size_t base4 = (size_t)posBase * 1024;      // 16 pos * 1024 float4
        #pragma unroll
        for (int i = 0; i < 32; ++i) {
            __stcs(outS4 + base4 + i * 512 + tid, z4);
            __stcs(outO4 + base4 + i * 512 + tid, z4);
        }
    }

    // --- Load x vectors for the 16 positions (16 x 32 = 512 elems) ---
    {
        int p = tid & 15, d = tid >> 4;
        xvs[p * 32 + d] = x[((size_t)(nm * Dq + d)) * HWq + hw0 + p];
    }
    __syncthreads();
    if (tid < 16) {
        float s = 0.0f;
        #pragma unroll
        for (int d = 0; d < 32; ++d) { float v = xvs[tid * 32 + d]; s += v * v; }
        x2s[tid] = s;
    }
    __syncthreads();

    const float lbt = fmaxf(temp[m], EPSF);          // lower_bound(temperature)
    const float lsc = -0.015625f * lbt;              // (-1/64) * lb(temp)
    const float4* cb4 = (const float4*)(cb + (size_t)m * Kq * Dq);
    const float* c2m = g_c2 + m * Kq;
    const float* thm = g_thresh + m * Kq;
    const uint32_t cbs_base = (uint32_t)__cvta_generic_to_shared(cbs);

    float x2r[4];
    #pragma unroll
    for (int p = 0; p < 4; ++p) x2r[p] = x2s[grp * 4 + p];
    const size_t offBase = ((size_t)(posBase + grp * 4)) * Kq;

    float lmv[4], smv[4]; int lix[4], six[4];
    #pragma unroll
    for (int p = 0; p < 4; ++p) { lmv[p] = -3.4e38f; smv[p] = -3.4e38f; lix[p] = 0; six[p] = 0; }

    for (int t = 0; t < 8; ++t) {
        // --- cp.async fill of 512-row tile into permuted stride-36 layout ---
        #pragma unroll
        for (int i = 0; i < 8; ++i) {
            int idx = i * 512 + tid;
            int row = idx >> 3, d4 = idx & 7;
            uint32_t dst = cbs_base + (uint32_t)((((row >> 2) + (row & 3) * 128) * 36 + d4 * 4) * 4);
            cp16(dst, cb4 + (size_t)(t * 512 + row) * 8 + d4);
        }
        asm volatile("cp.async.commit_group;");
        asm volatile("cp.async.wait_group 0;");
        __syncthreads();

        // --- Register-tiled dots: 4 consecutive k x 4 positions ---
        float acc[4][4];
        #pragma unroll
        for (int c = 0; c < 4; ++c)
            #pragma unroll
            for (int p = 0; p < 4; ++p) acc[c][p] = 0.0f;

        #pragma unroll
        for (int dc = 0; dc < 8; ++dc) {
            float4 xp[4];
            #pragma unroll
            for (int p = 0; p < 4; ++p)
                xp[p] = *(const float4*)&xvs[(grp * 4 + p) * 32 + dc * 4];
            #pragma unroll
            for (int c = 0; c < 4; ++c) {
                const float4 cv = *(const float4*)&cbs[(c * 128 + jj) * 36 + dc * 4];
                #pragma unroll
                for (int p = 0; p < 4; ++p) {
                    acc[c][p] = fmaf(cv.x, xp[p].x, acc[c][p]);
                    acc[c][p] = fmaf(cv.y, xp[p].y, acc[c][p]);
                    acc[c][p] = fmaf(cv.z, xp[p].z, acc[c][p]);
                    acc[c][p] = fmaf(cv.w, xp[p].w, acc[c][p]);
                }
            }
        }

        // --- Epilogue: vector loads, logit/s, streaming 128-bit stores, argmaxes ---
        {
            const int k0 = t * 512 + 4 * jj;
            const float4 c2 = __ldg((const float4*)(c2m + k0));
            const float4 th = __ldg((const float4*)(thm + k0));
            #pragma unroll
            for (int p = 0; p < 4; ++p) {
                const size_t off = offBase + (size_t)p * Kq + k0;
                const float4 dn = __ldcs((const float4*)(drop + off));
                const float4 gn = __ldcs((const float4*)(gum  + off));
                float4 lg;
                lg.x = ((x2r[p] + c2.x) - 2.0f * acc[0][p]) * lsc;
                lg.y = ((x2r[p] + c2.y) - 2.0f * acc[1][p]) * lsc;
                lg.z = ((x2r[p] + c2.z) - 2.0f * acc[2][p]) * lsc;
                lg.w = ((x2r[p] + c2.w) - 2.0f * acc[3][p]) * lsc;
                if (dn.x < th.x) lg.x += NEGINF;
                if (dn.y < th.y) lg.y += NEGINF;
                if (dn.z < th.z) lg.z += NEGINF;
                if (dn.w < th.w) lg.w += NEGINF;
                __stcs((float4*)(out + LOGIT_OFF + off), lg);
                // running argmaxes (k ascending in thread -> strict > keeps lowest)
                if (lg.x > lmv[p]) { lmv[p] = lg.x; lix[p] = k0 + 0; }
                if (lg.y > lmv[p]) { lmv[p] = lg.y; lix[p] = k0 + 1; }
                if (lg.z > lmv[p]) { lmv[p] = lg.z; lix[p] = k0 + 2; }
                if (lg.w > lmv[p]) { lmv[p] = lg.w; lix[p] = k0 + 3; }
                float sv;
                sv = lg.x + gn.x; if (sv > smv[p]) { smv[p] = sv; six[p] = k0 + 0; }
                sv = lg.y + gn.y; if (sv > smv[p]) { smv[p] = sv; six[p] = k0 + 1; }
                sv = lg.z + gn.z; if (sv > smv[p]) { smv[p] = sv; six[p] = k0 + 2; }
                sv = lg.w + gn.w; if (sv > smv[p]) { smv[p] = sv; six[p] = k0 + 3; }
            }
        }
        __syncthreads();   // all reads of cbs done before next fill overwrites
    }

    // --- Block-wide argmax reductions (tie -> lowest k, matching jnp.argmax) ---
    #pragma unroll
    for (int p = 0; p < 4; ++p) {
        int pp = grp * 4 + p;
        float v = lmv[p]; int ix = lix[p];
        for (int o = 16; o; o >>= 1) {
            float ov = __shfl_down_sync(0xffffffffu, v, o);
            int   oi = __shfl_down_sync(0xffffffffu, ix, o);
            if (ov > v || (ov == v && oi < ix)) { v = ov; ix = oi; }
        }
        if (lane == 0) { scV[pp * 4 + wig] = v; scI[pp * 4 + wig] = ix; }
        v = smv[p]; ix = six[p];
        for (int o = 16; o; o >>= 1) {
            float ov = __shfl_down_sync(0xffffffffu, v, o);
            int   oi = __shfl_down_sync(0xffffffffu, ix, o);
            if (ov > v || (ov == v && oi < ix)) { v = ov; ix = oi; }
        }
        if (lane == 0) { scV2[pp * 4 + wig] = v; scI2[pp * 4 + wig] = ix; }
    }
    __syncthreads();   // also orders the zero-fill stores before the scatters below

    if (tid < 16) {
        float bv = -3.4e38f; int li = 0;
        for (int w = 0; w < 4; ++w) {
            float v = scV[tid * 4 + w]; int i2 = scI[tid * 4 + w];
            if (v > bv || (v == bv && i2 < li)) { bv = v; li = i2; }
        }
        bv = -3.4e38f; int si = 0;
        for (int w = 0; w < 4; ++w) {
            float v = scV2[tid * 4 + w]; int i2 = scI2[tid * 4 + w];
            if (v > bv || (v == bv && i2 < si)) { bv = v; si = i2; }
        }
        size_t base = ((size_t)(posBase + tid)) * Kq;
        out[CODE_OFF + (size_t)(posBase + tid)] = (float)li;
        out[ONEHOT_OFF + base + li] = 1.0f;
        out[SAMPLE_OFF + base + si] = 1.0f;   // (1+y)-y == 1.0 within 1 ulp
    }
}

// ---------------- launch ----------------
extern "C" void kernel_launch(void* const* d_in, const int* in_sizes, int n_in,
                              void* d_out, int out_size) {
    const float* x    = (const float*)d_in[0];
    const float* cb   = (const float*)d_in[1];
    const float* freq = (const float*)d_in[2];
    const float* temp = (const float*)d_in[3];
    const float* drop = (const float*)d_in[4];
    const float* gum  = (const float*)d_in[5];
    float* out = (float*)d_out;

    const int smemBytes = (18432 + 512 + 16 + 64 * 4) * 4;  // ~76.9 KB
    cudaFuncSetAttribute(k_main, cudaFuncAttributeMaxDynamicSharedMemorySize, smemBytes);

    k_usage<<<1, 256>>>(freq);
    k_prep<<<32, 512>>>(freq, cb);
    k_main<<<1024, 512, smemBytes>>>(x, cb, temp, drop, gum, out);
}